// round 14
// baseline (speedup 1.0000x reference)
#include <cuda_runtime.h>
#include <cstdint>

// ---------------- model constants ----------------
#define TT     3
#define LL     3
#define EE     50000
#define NN     1000000
#define RRR    200
#define NRELC  401
#define HHH    256
#define TOPKC  1000
#define BBB    8
#define K32    32
#define NB_LSTM 96
#define NBSB   512
#define NBCP   740   // 148 SMs x 5 blocks, all co-resident at launch_bounds(256,5)

// ---------------- device scratch ----------------
__device__ float g_x[EE * K32];
__device__ float g_s[EE * K32];
__device__ unsigned char g_actb[EE];
__device__ float g_w[TT * NRELC * K32];
__device__ float g_pre[6 * 4 * BBB * 1024];
__device__ float g_h[6 * 4 * BBB * HHH];
__device__ float g_th[K32];
__device__ float g_sums[TT][K32];
__device__ int   g_cnt[1];
__device__ unsigned long long g_list[2 * NN];
__device__ int      g_ccnt[24];
__device__ unsigned g_cand[24 * EE];
__device__ unsigned g_barw = 0;      // LSTM barrier (96 blocks, 256-packing)
__device__ unsigned g_barw2 = 0;     // select_build barrier (512 blocks, 1024-packing)
__device__ unsigned g_barw3 = 0;     // hop barrier (740 blocks, 1024-packing)

__device__ __forceinline__ float sigf(float x) { return 1.0f / (1.0f + expf(-x)); }
__device__ __forceinline__ float dot4(float4 a, float4 b) {
    return a.x * b.x + a.y * b.y + a.z * b.z + a.w * b.w;
}

// Replay-safe grid barriers: packed word = gen*W + count; every barrier adds
// exactly W, so gen is monotone across graph replays.
__device__ __forceinline__ void gbarL() {
    __threadfence();
    __syncthreads();
    if (threadIdx.x == 0) {
        unsigned old = atomicAdd(&g_barw, 1u);
        unsigned gen = old >> 8;
        if ((old & 255u) == NB_LSTM - 1) atomicAdd(&g_barw, 256u - NB_LSTM);
        else while (((*(volatile unsigned*)&g_barw) >> 8) == gen) __nanosleep(64);
    }
    __syncthreads();
    __threadfence();
}

__device__ __forceinline__ void gbarSB() {
    __threadfence();
    __syncthreads();
    if (threadIdx.x == 0) {
        unsigned old = atomicAdd(&g_barw2, 1u);
        unsigned gen = old >> 10;
        if ((old & 1023u) == NBSB - 1) atomicAdd(&g_barw2, 1024u - NBSB);
        else while (((*(volatile unsigned*)&g_barw2) >> 10) == gen) __nanosleep(64);
    }
    __syncthreads();
    __threadfence();
}

__device__ __forceinline__ void gbarCP() {
    __threadfence();
    __syncthreads();
    if (threadIdx.x == 0) {
        unsigned old = atomicAdd(&g_barw3, 1u);
        unsigned gen = old >> 10;
        if ((old & 1023u) == NBCP - 1) atomicAdd(&g_barw3, 1024u - NBCP);
        else while (((*(volatile unsigned*)&g_barw3) >> 10) == gen) __nanosleep(64);
    }
    __syncthreads();
    __threadfence();
}

// ---------------- LSTM input projections: 768 blocks, warp per row ----------------
__global__ void pre_kernel(const int* __restrict__ input_r, const float* __restrict__ emb,
                           const float* __restrict__ Wih_f, const float* __restrict__ bih_f,
                           const float* __restrict__ bhh_f,
                           const float* __restrict__ Wih_b, const float* __restrict__ bih_b,
                           const float* __restrict__ bhh_b) {
    int ld = blockIdx.y, l = ld >> 1, dir = ld & 1;
    const float* Wih = (dir ? Wih_b : Wih_f) + l * 1024 * HHH;
    const float* bih = (dir ? bih_b : bih_f) + l * 1024;
    const float* bhh = (dir ? bhh_b : bhh_f) + l * 1024;

    __shared__ float sv[9][HHH];
    __shared__ int sr[8];
    int tid = threadIdx.x;
    // housekeeping (consumed only by later kernels)
    if (blockIdx.x == 0 && blockIdx.y == 0) {
        for (int i = tid; i < TT * NRELC * K32; i += 256) g_w[i] = 0.0f;
        if (tid < TT * K32) ((float*)g_sums)[tid] = 0.0f;
    }
    if (tid < 8) sr[tid] = input_r[tid];
    __syncthreads();
    for (int i = tid; i < 9 * HHH; i += 256) {
        int v = i >> 8, c = i & 255;
        int rs = (v < 8) ? sr[v] : (NRELC - 1);
        sv[v][c] = emb[rs * HHH + c];
    }
    __syncthreads();

    int warp = tid >> 5, lane = tid & 31;
    int j = blockIdx.x * 8 + warp;
    const float4* w4 = (const float4*)(Wih + j * HHH);
    float4 w0 = w4[lane], w1 = w4[32 + lane];

    float acc[9];
    #pragma unroll
    for (int v = 0; v < 9; v++) {
        const float4* s4 = (const float4*)sv[v];
        acc[v] = dot4(w0, s4[lane]) + dot4(w1, s4[32 + lane]);
    }
    #pragma unroll
    for (int v = 0; v < 9; v++)
        #pragma unroll
        for (int o = 16; o; o >>= 1) acc[v] += __shfl_down_sync(0xFFFFFFFFu, acc[v], o);

    if (lane == 0) {
        float bb = bih[j] + bhh[j];
        #pragma unroll
        for (int t = 0; t < 4; t++)
            #pragma unroll
            for (int b = 0; b < 8; b++) {
                int v = dir ? ((t == 0) ? 8 : b) : ((t < 3) ? b : 8);
                g_pre[((ld * 4 + t) * BBB + b) * 1024 + j] = acc[v] + bb;
            }
    }
}

// ---------------- fused recurrent LSTM (4 steps) + wlin tail ----------------
__global__ __launch_bounds__(256, 1) void lstm_rec_kernel(
    const float* __restrict__ Whh_f, const float* __restrict__ Whh_b,
    const float* __restrict__ linW, const float* __restrict__ linb)
{
    int blk = blockIdx.x;
    int ld = blk >> 4, cg = blk & 15;
    int l = ld >> 1, dir = ld & 1;
    const float* Whh = (dir ? Whh_b : Whh_f) + l * 1024 * HHH;

    __shared__ float pre_s[4][8][64];
    __shared__ float sh[8][HHH];
    __shared__ float sc[8][16];
    __shared__ float sacc_s[4][16][8];
    __shared__ float s_logit[NRELC];
    __shared__ float s_red[256];

    int tid = threadIdx.x, lane = tid & 31, warp = tid >> 5;
    int gate = warp & 3, kc8 = (warp >> 2) * 8;

    float4 w[16];
    #pragma unroll
    for (int r = 0; r < 8; r++) {
        int j = gate * 256 + cg * 16 + kc8 + r;
        const float4* w4 = (const float4*)(Whh + j * HHH);
        w[2 * r] = w4[lane * 2]; w[2 * r + 1] = w4[lane * 2 + 1];
    }
    for (int i = tid; i < 4 * 8 * 64; i += 256) {
        int t = i >> 9, rem = i & 511;
        int b = rem >> 6, row = rem & 63;
        int gate2 = row >> 4, kc = row & 15;
        int j = gate2 * 256 + cg * 16 + kc;
        pre_s[t][b][row] = g_pre[((ld * 4 + t) * BBB + b) * 1024 + j];
    }
    __syncthreads();

    for (int t = 0; t < 4; t++) {
        if (t > 0) {
            const float* hp = &g_h[((ld * 4 + (t - 1)) * 8) * HHH];
            for (int i = tid; i < 8 * HHH; i += 256) ((float*)sh)[i] = hp[i];
            __syncthreads();
        }
        #pragma unroll
        for (int r = 0; r < 8; r++) {
            float acc[8];
            #pragma unroll
            for (int b = 0; b < 8; b++) {
                if (t > 0) {
                    const float4* h4 = (const float4*)sh[b];
                    acc[b] = dot4(w[2 * r], h4[lane * 2]) + dot4(w[2 * r + 1], h4[lane * 2 + 1]);
                } else acc[b] = 0.0f;
            }
            #pragma unroll
            for (int b = 0; b < 8; b++)
                #pragma unroll
                for (int o = 16; o; o >>= 1) acc[b] += __shfl_down_sync(0xFFFFFFFFu, acc[b], o);
            if (lane == 0) {
                int kc = kc8 + r;
                #pragma unroll
                for (int b = 0; b < 8; b++)
                    sacc_s[gate][kc][b] = acc[b] + pre_s[t][b][gate * 16 + kc];
            }
        }
        __syncthreads();
        if (tid < 128) {
            int kc = tid >> 3, b = tid & 7;
            float gi = sacc_s[0][kc][b], gf = sacc_s[1][kc][b];
            float gg = sacc_s[2][kc][b], go = sacc_s[3][kc][b];
            float cp = (t > 0) ? sc[b][kc] : 0.0f;
            float c = sigf(gf) * cp + sigf(gi) * tanhf(gg);
            float h = sigf(go) * tanhf(c);
            sc[b][kc] = c;
            g_h[((ld * 4 + t) * 8 + b) * HHH + cg * 16 + kc] = h;
        }
        gbarL();
    }

    // ---- wlin tail: blocks 0..71 each handle one (t,l,b) ----
    if (blk < 72) {
        int t = blk / 24, l2 = (blk % 24) / 8, b = blk % 8;
        float* rnn = (float*)sh;
        const float* hf = &g_h[(((l2 * 2 + 0) * 4 + t) * BBB + b) * HHH];
        const float* hb = &g_h[(((l2 * 2 + 1) * 4 + (3 - t)) * BBB + b) * HHH];
        for (int i = tid; i < HHH; i += 256) { rnn[i] = hf[i]; rnn[HHH + i] = hb[i]; }
        __syncthreads();
        const float4* r4 = (const float4*)rnn;
        for (int n = tid; n < NRELC; n += 256) {
            const float4* w4 = (const float4*)(linW + n * 2 * HHH);
            float acc = 0.0f;
            for (int kk = 0; kk < (2 * HHH) / 4; kk++) acc += dot4(w4[kk], r4[kk]);
            s_logit[n] = acc + linb[n];
        }
        __syncthreads();
        float m = -1e30f;
        for (int n = tid; n < NRELC; n += 256) m = fmaxf(m, s_logit[n]);
        s_red[tid] = m; __syncthreads();
        for (int o = 128; o; o >>= 1) { if (tid < o) s_red[tid] = fmaxf(s_red[tid], s_red[tid + o]); __syncthreads(); }
        m = s_red[0]; __syncthreads();
        float ssum = 0.0f;
        for (int n = tid; n < NRELC; n += 256) {
            float e = expf((s_logit[n] - m) / 10.0f);
            s_logit[n] = e; ssum += e;
        }
        s_red[tid] = ssum; __syncthreads();
        for (int o = 128; o; o >>= 1) { if (tid < o) s_red[tid] += s_red[tid + o]; __syncthreads(); }
        ssum = s_red[0];
        int k = b * 3 + l2;
        for (int n = tid; n < NRELC; n += 256)
            g_w[(t * NRELC + n) * K32 + k] = s_logit[n] / ssum;
    }
}

// ---------------- fused per-hop kernel: [buildx0 if t==0] + compact + prop ----------------
__global__ __launch_bounds__(256, 5) void hop_kernel(
    int t, const int* __restrict__ input_x,
    const int* __restrict__ heads, const int* __restrict__ tails,
    const int* __restrict__ tails2, const int* __restrict__ rels)
{
    const int blk = blockIdx.x, tid = threadIdx.x;
    const int lane = tid & 31, warp = tid >> 5;
    const int gtid = blk * 256 + tid;
    const int TOT = NBCP * 256;
    const int NWRP = NBCP * 8;
    const int gwarp = blk * 8 + warp;

    __shared__ int xs[BBB];
    __shared__ float sm[8][32];

    // ======== phase 0 (t==0 only): buildx0 ========
    if (t == 0) {
        if (tid < BBB) xs[tid] = input_x[tid];
        if (gtid == 0) g_cnt[0] = 0;
        __syncthreads();
        float wid = g_w[(NRELC - 1) * K32 + lane];
        int bsel = (lane < 24) ? (lane / 3) : 0;
        float sacc = 0.0f;
        for (int e = gwarp; e < EE; e += NWRP) {
            float x = (lane < 24 && xs[bsel] == e) ? 1.0f : 0.0f;
            unsigned nz = __ballot_sync(0xFFFFFFFFu, x != 0.0f);
            if (nz) g_x[e * K32 + lane] = x;
            float s = wid * x;
            g_s[e * K32 + lane] = s;
            sacc += s;
            if (lane == 0) g_actb[e] = nz ? 1 : 0;
        }
        sm[warp][lane] = sacc;
        __syncthreads();
        if (tid < 32) {
            float s = 0.0f;
            #pragma unroll
            for (int w = 0; w < 8; w++) s += sm[w][tid];
            if (s != 0.0f) atomicAdd(&g_sums[0][tid], s);
        }
        gbarCP();
    }

    // ======== phase 1: compact (int4 loads, warp-scan aggregation) ========
    {
        if (gtid < 24) g_ccnt[gtid] = 0;    // reset for NEXT hop's select
        const int4* h4p  = (const int4*)heads;
        const int4* t4p  = (const int4*)tails2;
        const int4* tl4p = (const int4*)tails;
        const int4* r4p  = (const int4*)rels;
        const int nq = NN / 4;
        const int iters = (nq + TOT - 1) / TOT;
        for (int it = 0; it < iters; it++) {
            int q = gtid + it * TOT;
            bool valid = q < nq;
            int4 h4 = {0,0,0,0}, t4 = {0,0,0,0};
            int a0 = 0, a1 = 0, a2 = 0, a3 = 0, b0 = 0, b1 = 0, b2 = 0, b3 = 0;
            int cnt = 0;
            if (valid) {
                h4 = h4p[q]; t4 = t4p[q];
                a0 = g_actb[h4.x]; a1 = g_actb[h4.y]; a2 = g_actb[h4.z]; a3 = g_actb[h4.w];
                b0 = g_actb[t4.x]; b1 = g_actb[t4.y]; b2 = g_actb[t4.z]; b3 = g_actb[t4.w];
                cnt = a0 + a1 + a2 + a3 + b0 + b1 + b2 + b3;
            }
            unsigned any = __ballot_sync(0xFFFFFFFFu, cnt > 0);
            if (!any) continue;
            int pre = cnt;
            #pragma unroll
            for (int o = 1; o < 32; o <<= 1) {
                int v = __shfl_up_sync(0xFFFFFFFFu, pre, o);
                if (lane >= o) pre += v;
            }
            int total = __shfl_sync(0xFFFFFFFFu, pre, 31);
            int base;
            if (lane == 31) base = atomicAdd(&g_cnt[0], total);
            base = __shfl_sync(0xFFFFFFFFu, base, 31);
            int off = base + pre - cnt;
            if (cnt) {
                int4 r4v = r4p[q];
                int4 tl4 = tl4p[q];
                if (a0) g_list[off++] = (((unsigned long long)r4v.x) << 32) | ((unsigned)tl4.x << 16) | (unsigned)h4.x;
                if (b0) g_list[off++] = (((unsigned long long)(r4v.x + RRR)) << 32) | ((unsigned)h4.x << 16) | (unsigned)t4.x;
                if (a1) g_list[off++] = (((unsigned long long)r4v.y) << 32) | ((unsigned)tl4.y << 16) | (unsigned)h4.y;
                if (b1) g_list[off++] = (((unsigned long long)(r4v.y + RRR)) << 32) | ((unsigned)h4.y << 16) | (unsigned)t4.y;
                if (a2) g_list[off++] = (((unsigned long long)r4v.z) << 32) | ((unsigned)tl4.z << 16) | (unsigned)h4.z;
                if (b2) g_list[off++] = (((unsigned long long)(r4v.z + RRR)) << 32) | ((unsigned)h4.z << 16) | (unsigned)t4.z;
                if (a3) g_list[off++] = (((unsigned long long)r4v.w) << 32) | ((unsigned)tl4.w << 16) | (unsigned)h4.w;
                if (b3) g_list[off++] = (((unsigned long long)(r4v.w + RRR)) << 32) | ((unsigned)h4.w << 16) | (unsigned)t4.w;
            }
        }
    }
    gbarCP();

    // ======== phase 2: propagate over packed list + sums ========
    {
        const float* wt = &g_w[t * NRELC * K32];
        int cnt = g_cnt[0];
        float sacc = 0.0f;
        for (int j0 = gwarp * 4; j0 < cnt; j0 += NWRP * 4) {
            int n = min(4, cnt - j0);
            unsigned long long e[4];
            #pragma unroll
            for (int u = 0; u < 4; u++) if (u < n) e[u] = g_list[j0 + u];
            float xv[4], wv[4];
            #pragma unroll
            for (int u = 0; u < 4; u++) if (u < n) {
                int src = (int)(e[u] & 0xFFFFu);
                int rel = (int)(e[u] >> 32);
                xv[u] = g_x[src * K32 + lane];
                wv[u] = wt[rel * K32 + lane];
            }
            #pragma unroll
            for (int u = 0; u < 4; u++) if (u < n) {
                int dst = (int)((e[u] >> 16) & 0xFFFFu);
                float mm = xv[u] * wv[u];
                sacc += mm;
                if (mm != 0.0f) atomicAdd(&g_s[dst * K32 + lane], mm);
            }
        }
        __syncthreads();
        sm[warp][lane] = sacc;
        __syncthreads();
        if (tid < 32) {
            float s = 0.0f;
            #pragma unroll
            for (int w = 0; w < 8; w++) s += sm[w][tid];
            if (s != 0.0f) atomicAdd(&g_sums[t][tid], s);
        }
    }
}

// ---------------- select_build: nzc + sel + buildx fused (512 blocks) ----------------
__global__ __launch_bounds__(256, 4) void select_build_kernel(int t) {
    const int blk = blockIdx.x, tid = threadIdx.x;
    const int lane = tid & 31, warp = tid >> 5;
    const int gtid = blk * 256 + tid;
    const int TOT = NBSB * 256;
    __shared__ unsigned s_h[256], s_scan[256];
    __shared__ unsigned s_pref, s_need;
    __shared__ float sm[8][32];

    // ---- phase 1: nzc (compact nonzero s values per channel) ----
    for (int i = gtid; i < EE * K32; i += TOT) {
        int k = i & 31;
        if (k < 24) {
            float v = g_s[i];
            if (v != 0.0f) {
                int off = atomicAdd(&g_ccnt[k], 1);
                g_cand[k * EE + off] = __float_as_uint(v);
            }
        }
    }
    gbarSB();

    // ---- phase 2: exact top-k threshold (blocks 0..23) ----
    if (blk < 24) {
        int k = blk;
        int cnt = g_ccnt[k];
        if (cnt < TOPKC) {
            if (tid == 0) g_th[k] = 0.0f;
        } else {
            unsigned pref = 0, need = TOPKC;
            const unsigned* cand = &g_cand[k * EE];
            for (int p = 3; p >= 0; p--) {
                s_h[tid] = 0u;
                __syncthreads();
                for (int i = tid; i < cnt; i += 256) {
                    unsigned u = cand[i];
                    bool ok = (p == 3) || ((u >> (8 * p + 8)) == pref);
                    if (ok) atomicAdd(&s_h[(u >> (8 * p)) & 255u], 1u);
                }
                __syncthreads();
                s_scan[tid] = s_h[tid];
                __syncthreads();
                for (int o = 1; o < 256; o <<= 1) {
                    unsigned add = (tid + o < 256) ? s_scan[tid + o] : 0u;
                    __syncthreads();
                    s_scan[tid] += add;
                    __syncthreads();
                }
                unsigned cumIncl = s_scan[tid];
                unsigned cumAbove = cumIncl - s_h[tid];
                if (cumIncl >= need && cumAbove < need) {
                    s_pref = (pref << 8) | (unsigned)tid;
                    s_need = need - cumAbove;
                }
                __syncthreads();
                pref = s_pref; need = s_need;
                __syncthreads();
            }
            if (tid == 0) g_th[k] = __uint_as_float(pref);
        }
    }
    gbarSB();

    // ---- phase 3: buildx for hop t ----
    {
        if (gtid == 0) g_cnt[0] = 0;
        const int NWRP = NBSB * 8;
        int gwarp = blk * 8 + warp;
        float wid = g_w[(t * NRELC + (NRELC - 1)) * K32 + lane];
        float th = g_th[lane];
        float den = fmaxf(g_sums[t - 1][lane], 1e-7f);
        float sacc = 0.0f;
        for (int e = gwarp; e < EE; e += NWRP) {
            float v = g_s[e * K32 + lane];
            float x = (v >= th) ? (v / den) : 0.0f;
            unsigned nz = __ballot_sync(0xFFFFFFFFu, x != 0.0f);
            if (nz) g_x[e * K32 + lane] = x;
            float s = wid * x;
            g_s[e * K32 + lane] = s;
            sacc += s;
            if (lane == 0) g_actb[e] = nz ? 1 : 0;
        }
        __syncthreads();
        sm[warp][lane] = sacc;
        __syncthreads();
        if (tid < 32) {
            float s = 0.0f;
            #pragma unroll
            for (int w = 0; w < 8; w++) s += sm[w][tid];
            if (s != 0.0f) atomicAdd(&g_sums[t][tid], s);
        }
    }
}

// ---------------- final output: transposed coalesced writes ----------------
__global__ void out_kernel(float* __restrict__ out) {
    __shared__ float s_tile[8][32][33];
    __shared__ float s_den[24];
    int tid = threadIdx.x, lane = tid & 31, warp = tid >> 5;
    if (tid < 24) s_den[tid] = 1.0f / fmaxf(g_sums[TT - 1][tid], 1e-7f);
    __syncthreads();
    int gwarp = blockIdx.x * 8 + warp;
    int nw = gridDim.x * 8;
    for (int e0 = gwarp * 32; e0 < EE; e0 += nw * 32) {
        #pragma unroll 4
        for (int j = 0; j < 32; j++) {
            int e = e0 + j;
            s_tile[warp][j][lane] = (e < EE) ? g_s[e * K32 + lane] : 0.0f;
        }
        __syncwarp();
        int e = e0 + lane;
        if (e < EE) {
            #pragma unroll
            for (int b = 0; b < 8; b++) {
                float a = 0.0f;
                #pragma unroll
                for (int l = 0; l < 3; l++)
                    a += s_tile[warp][lane][b * 3 + l] * s_den[b * 3 + l];
                out[b * EE + e] = a;
            }
        }
        __syncwarp();
    }
}

// ---------------- launch ----------------
extern "C" void kernel_launch(void* const* d_in, const int* in_sizes, int n_in,
                              void* d_out, int out_size) {
    const int*   input_x  = (const int*)d_in[0];
    const int*   input_r  = (const int*)d_in[1];
    const int*   e2triple = (const int*)d_in[2];
    const int*   triple2e = (const int*)d_in[3];
    const int*   r2triple = (const int*)d_in[4];
    const float* emb      = (const float*)d_in[5];
    const float* Wih_f    = (const float*)d_in[6];
    const float* Whh_f    = (const float*)d_in[7];
    const float* bih_f    = (const float*)d_in[8];
    const float* bhh_f    = (const float*)d_in[9];
    const float* Wih_b    = (const float*)d_in[10];
    const float* Whh_b    = (const float*)d_in[11];
    const float* bih_b    = (const float*)d_in[12];
    const float* bhh_b    = (const float*)d_in[13];
    const float* linW     = (const float*)d_in[14];
    const float* linb     = (const float*)d_in[15];

    const int* heads  = e2triple;
    const int* tails2 = e2triple + 2 * NN;
    const int* tails  = triple2e + NN;
    const int* rels   = r2triple;

    pre_kernel<<<dim3(128, 6), 256>>>(input_r, emb, Wih_f, bih_f, bhh_f,
                                      Wih_b, bih_b, bhh_b);
    lstm_rec_kernel<<<NB_LSTM, 256>>>(Whh_f, Whh_b, linW, linb);

    for (int t = 0; t < TT; t++) {
        if (t > 0) select_build_kernel<<<NBSB, 256>>>(t);
        hop_kernel<<<NBCP, 256>>>(t, input_x, heads, tails, tails2, rels);
    }

    out_kernel<<<256, 256>>>((float*)d_out);
}

// round 15
// speedup vs baseline: 1.1641x; 1.1641x over previous
#include <cuda_runtime.h>
#include <cstdint>

// ---------------- model constants ----------------
#define TT     3
#define LL     3
#define EE     50000
#define NN     1000000
#define RRR    200
#define NRELC  401
#define HHH    256
#define TOPKC  1000
#define BBB    8
#define K32    32
#define NB_LSTM 96
#define NBSB   512

// ---------------- device scratch ----------------
__device__ float g_x[EE * K32];
__device__ float g_s[EE * K32];
__device__ unsigned char g_actb[EE];
__device__ float g_w[TT * NRELC * K32];
__device__ float g_pre[6 * 4 * BBB * 1024];
__device__ float g_h[6 * 4 * BBB * HHH];
__device__ float g_th[K32];
__device__ float g_sums[TT][K32];
__device__ int   g_cnt[1];
__device__ unsigned long long g_list[2 * NN];
__device__ int      g_ccnt[24];
__device__ unsigned g_cand[24 * EE];
__device__ unsigned g_barw = 0;      // LSTM barrier (96 blocks, 256-packing)
__device__ unsigned g_barw2 = 0;     // select_build barrier (512 blocks, 1024-packing)

__device__ __forceinline__ float sigf(float x) { return 1.0f / (1.0f + expf(-x)); }
__device__ __forceinline__ float dot4(float4 a, float4 b) {
    return a.x * b.x + a.y * b.y + a.z * b.z + a.w * b.w;
}

// Replay-safe grid barriers: packed word = gen*W + count; every barrier adds
// exactly W, so gen is monotone across graph replays.
__device__ __forceinline__ void gbarL() {
    __threadfence();
    __syncthreads();
    if (threadIdx.x == 0) {
        unsigned old = atomicAdd(&g_barw, 1u);
        unsigned gen = old >> 8;
        if ((old & 255u) == NB_LSTM - 1) atomicAdd(&g_barw, 256u - NB_LSTM);
        else while (((*(volatile unsigned*)&g_barw) >> 8) == gen) __nanosleep(64);
    }
    __syncthreads();
    __threadfence();
}

__device__ __forceinline__ void gbarSB() {
    __threadfence();
    __syncthreads();
    if (threadIdx.x == 0) {
        unsigned old = atomicAdd(&g_barw2, 1u);
        unsigned gen = old >> 10;
        if ((old & 1023u) == NBSB - 1) atomicAdd(&g_barw2, 1024u - NBSB);
        else while (((*(volatile unsigned*)&g_barw2) >> 10) == gen) __nanosleep(64);
    }
    __syncthreads();
    __threadfence();
}

// ---------------- LSTM input projections: 768 blocks, warp per row ----------------
__global__ void pre_kernel(const int* __restrict__ input_r, const float* __restrict__ emb,
                           const float* __restrict__ Wih_f, const float* __restrict__ bih_f,
                           const float* __restrict__ bhh_f,
                           const float* __restrict__ Wih_b, const float* __restrict__ bih_b,
                           const float* __restrict__ bhh_b) {
    int ld = blockIdx.y, l = ld >> 1, dir = ld & 1;
    const float* Wih = (dir ? Wih_b : Wih_f) + l * 1024 * HHH;
    const float* bih = (dir ? bih_b : bih_f) + l * 1024;
    const float* bhh = (dir ? bhh_b : bhh_f) + l * 1024;

    __shared__ float sv[9][HHH];
    __shared__ int sr[8];
    int tid = threadIdx.x;
    // housekeeping (consumed only by later kernels)
    if (blockIdx.x == 0 && blockIdx.y == 0) {
        for (int i = tid; i < TT * NRELC * K32; i += 256) g_w[i] = 0.0f;
        if (tid < TT * K32) ((float*)g_sums)[tid] = 0.0f;
    }
    if (tid < 8) sr[tid] = input_r[tid];
    __syncthreads();
    for (int i = tid; i < 9 * HHH; i += 256) {
        int v = i >> 8, c = i & 255;
        int rs = (v < 8) ? sr[v] : (NRELC - 1);
        sv[v][c] = emb[rs * HHH + c];
    }
    __syncthreads();

    int warp = tid >> 5, lane = tid & 31;
    int j = blockIdx.x * 8 + warp;
    const float4* w4 = (const float4*)(Wih + j * HHH);
    float4 w0 = w4[lane], w1 = w4[32 + lane];

    float acc[9];
    #pragma unroll
    for (int v = 0; v < 9; v++) {
        const float4* s4 = (const float4*)sv[v];
        acc[v] = dot4(w0, s4[lane]) + dot4(w1, s4[32 + lane]);
    }
    #pragma unroll
    for (int v = 0; v < 9; v++)
        #pragma unroll
        for (int o = 16; o; o >>= 1) acc[v] += __shfl_down_sync(0xFFFFFFFFu, acc[v], o);

    if (lane == 0) {
        float bb = bih[j] + bhh[j];
        #pragma unroll
        for (int t = 0; t < 4; t++)
            #pragma unroll
            for (int b = 0; b < 8; b++) {
                int v = dir ? ((t == 0) ? 8 : b) : ((t < 3) ? b : 8);
                g_pre[((ld * 4 + t) * BBB + b) * 1024 + j] = acc[v] + bb;
            }
    }
}

// ---------------- fused recurrent LSTM (4 steps) + wlin tail ----------------
__global__ __launch_bounds__(256, 1) void lstm_rec_kernel(
    const float* __restrict__ Whh_f, const float* __restrict__ Whh_b,
    const float* __restrict__ linW, const float* __restrict__ linb)
{
    int blk = blockIdx.x;
    int ld = blk >> 4, cg = blk & 15;
    int l = ld >> 1, dir = ld & 1;
    const float* Whh = (dir ? Whh_b : Whh_f) + l * 1024 * HHH;

    __shared__ float pre_s[4][8][64];
    __shared__ float sh[8][HHH];
    __shared__ float sc[8][16];
    __shared__ float sacc_s[4][16][8];
    __shared__ float s_logit[NRELC];
    __shared__ float s_red[256];

    int tid = threadIdx.x, lane = tid & 31, warp = tid >> 5;
    int gate = warp & 3, kc8 = (warp >> 2) * 8;

    float4 w[16];
    #pragma unroll
    for (int r = 0; r < 8; r++) {
        int j = gate * 256 + cg * 16 + kc8 + r;
        const float4* w4 = (const float4*)(Whh + j * HHH);
        w[2 * r] = w4[lane * 2]; w[2 * r + 1] = w4[lane * 2 + 1];
    }
    for (int i = tid; i < 4 * 8 * 64; i += 256) {
        int t = i >> 9, rem = i & 511;
        int b = rem >> 6, row = rem & 63;
        int gate2 = row >> 4, kc = row & 15;
        int j = gate2 * 256 + cg * 16 + kc;
        pre_s[t][b][row] = g_pre[((ld * 4 + t) * BBB + b) * 1024 + j];
    }
    __syncthreads();

    for (int t = 0; t < 4; t++) {
        if (t > 0) {
            const float* hp = &g_h[((ld * 4 + (t - 1)) * 8) * HHH];
            for (int i = tid; i < 8 * HHH; i += 256) ((float*)sh)[i] = hp[i];
            __syncthreads();
        }
        #pragma unroll
        for (int r = 0; r < 8; r++) {
            float acc[8];
            #pragma unroll
            for (int b = 0; b < 8; b++) {
                if (t > 0) {
                    const float4* h4 = (const float4*)sh[b];
                    acc[b] = dot4(w[2 * r], h4[lane * 2]) + dot4(w[2 * r + 1], h4[lane * 2 + 1]);
                } else acc[b] = 0.0f;
            }
            #pragma unroll
            for (int b = 0; b < 8; b++)
                #pragma unroll
                for (int o = 16; o; o >>= 1) acc[b] += __shfl_down_sync(0xFFFFFFFFu, acc[b], o);
            if (lane == 0) {
                int kc = kc8 + r;
                #pragma unroll
                for (int b = 0; b < 8; b++)
                    sacc_s[gate][kc][b] = acc[b] + pre_s[t][b][gate * 16 + kc];
            }
        }
        __syncthreads();
        if (tid < 128) {
            int kc = tid >> 3, b = tid & 7;
            float gi = sacc_s[0][kc][b], gf = sacc_s[1][kc][b];
            float gg = sacc_s[2][kc][b], go = sacc_s[3][kc][b];
            float cp = (t > 0) ? sc[b][kc] : 0.0f;
            float c = sigf(gf) * cp + sigf(gi) * tanhf(gg);
            float h = sigf(go) * tanhf(c);
            sc[b][kc] = c;
            g_h[((ld * 4 + t) * 8 + b) * HHH + cg * 16 + kc] = h;
        }
        gbarL();
    }

    // ---- wlin tail: blocks 0..71 each handle one (t,l,b) ----
    if (blk < 72) {
        int t = blk / 24, l2 = (blk % 24) / 8, b = blk % 8;
        float* rnn = (float*)sh;
        const float* hf = &g_h[(((l2 * 2 + 0) * 4 + t) * BBB + b) * HHH];
        const float* hb = &g_h[(((l2 * 2 + 1) * 4 + (3 - t)) * BBB + b) * HHH];
        for (int i = tid; i < HHH; i += 256) { rnn[i] = hf[i]; rnn[HHH + i] = hb[i]; }
        __syncthreads();
        const float4* r4 = (const float4*)rnn;
        for (int n = tid; n < NRELC; n += 256) {
            const float4* w4 = (const float4*)(linW + n * 2 * HHH);
            float acc = 0.0f;
            for (int kk = 0; kk < (2 * HHH) / 4; kk++) acc += dot4(w4[kk], r4[kk]);
            s_logit[n] = acc + linb[n];
        }
        __syncthreads();
        float m = -1e30f;
        for (int n = tid; n < NRELC; n += 256) m = fmaxf(m, s_logit[n]);
        s_red[tid] = m; __syncthreads();
        for (int o = 128; o; o >>= 1) { if (tid < o) s_red[tid] = fmaxf(s_red[tid], s_red[tid + o]); __syncthreads(); }
        m = s_red[0]; __syncthreads();
        float ssum = 0.0f;
        for (int n = tid; n < NRELC; n += 256) {
            float e = expf((s_logit[n] - m) / 10.0f);
            s_logit[n] = e; ssum += e;
        }
        s_red[tid] = ssum; __syncthreads();
        for (int o = 128; o; o >>= 1) { if (tid < o) s_red[tid] += s_red[tid + o]; __syncthreads(); }
        ssum = s_red[0];
        int k = b * 3 + l2;
        for (int n = tid; n < NRELC; n += 256)
            g_w[(t * NRELC + n) * K32 + k] = s_logit[n] / ssum;
    }
}

// ---------------- buildx0 (identity-init + activity + sums) ----------------
__global__ void buildx0_kernel(const int* __restrict__ input_x) {
    __shared__ int xs[BBB];
    __shared__ float sm[8][32];
    if (threadIdx.x < BBB) xs[threadIdx.x] = input_x[threadIdx.x];
    __syncthreads();
    int gtid = blockIdx.x * blockDim.x + threadIdx.x;
    if (gtid == 0) g_cnt[0] = 0;
    int lane = threadIdx.x & 31;
    int warp = gtid >> 5;
    int nw = (gridDim.x * blockDim.x) >> 5;
    float wid = g_w[(NRELC - 1) * K32 + lane];
    int bsel = (lane < 24) ? (lane / 3) : 0;
    float sacc = 0.0f;
    for (int e = warp; e < EE; e += nw) {
        float x = (lane < 24 && xs[bsel] == e) ? 1.0f : 0.0f;
        unsigned nz = __ballot_sync(0xFFFFFFFFu, x != 0.0f);
        if (nz) g_x[e * K32 + lane] = x;
        float s = wid * x;
        g_s[e * K32 + lane] = s;
        sacc += s;
        if (lane == 0) g_actb[e] = nz ? 1 : 0;
    }
    sm[threadIdx.x >> 5][lane] = sacc;
    __syncthreads();
    if (threadIdx.x < 32) {
        float s = 0.0f;
        #pragma unroll
        for (int w = 0; w < 8; w++) s += sm[w][threadIdx.x];
        if (s != 0.0f) atomicAdd(&g_sums[0][threadIdx.x], s);
    }
}

// ---------------- compact: int4 loads, warp-scan aggregation ----------------
__global__ void compact_kernel(const int* __restrict__ heads, const int* __restrict__ tails,
                               const int* __restrict__ tails2, const int* __restrict__ rels) {
    int gtid = blockIdx.x * blockDim.x + threadIdx.x;
    if (gtid < 24) g_ccnt[gtid] = 0;    // reset for NEXT hop's select
    int lane = threadIdx.x & 31;
    int tot = gridDim.x * blockDim.x;
    const int4* h4p  = (const int4*)heads;
    const int4* t4p  = (const int4*)tails2;
    const int4* tl4p = (const int4*)tails;
    const int4* r4p  = (const int4*)rels;
    const int nq = NN / 4;
    const int iters = (nq + tot - 1) / tot;

    for (int it = 0; it < iters; it++) {
        int q = gtid + it * tot;
        bool valid = q < nq;
        int4 h4 = {0,0,0,0}, t4 = {0,0,0,0};
        int a0 = 0, a1 = 0, a2 = 0, a3 = 0, b0 = 0, b1 = 0, b2 = 0, b3 = 0;
        int cnt = 0;
        if (valid) {
            h4 = h4p[q]; t4 = t4p[q];
            a0 = g_actb[h4.x]; a1 = g_actb[h4.y]; a2 = g_actb[h4.z]; a3 = g_actb[h4.w];
            b0 = g_actb[t4.x]; b1 = g_actb[t4.y]; b2 = g_actb[t4.z]; b3 = g_actb[t4.w];
            cnt = a0 + a1 + a2 + a3 + b0 + b1 + b2 + b3;
        }
        unsigned any = __ballot_sync(0xFFFFFFFFu, cnt > 0);
        if (!any) continue;
        int pre = cnt;
        #pragma unroll
        for (int o = 1; o < 32; o <<= 1) {
            int v = __shfl_up_sync(0xFFFFFFFFu, pre, o);
            if (lane >= o) pre += v;
        }
        int total = __shfl_sync(0xFFFFFFFFu, pre, 31);
        int base;
        if (lane == 31) base = atomicAdd(&g_cnt[0], total);
        base = __shfl_sync(0xFFFFFFFFu, base, 31);
        int off = base + pre - cnt;
        if (cnt) {
            int4 r4v = r4p[q];
            int4 tl4 = tl4p[q];
            if (a0) g_list[off++] = (((unsigned long long)r4v.x) << 32) | ((unsigned)tl4.x << 16) | (unsigned)h4.x;
            if (b0) g_list[off++] = (((unsigned long long)(r4v.x + RRR)) << 32) | ((unsigned)h4.x << 16) | (unsigned)t4.x;
            if (a1) g_list[off++] = (((unsigned long long)r4v.y) << 32) | ((unsigned)tl4.y << 16) | (unsigned)h4.y;
            if (b1) g_list[off++] = (((unsigned long long)(r4v.y + RRR)) << 32) | ((unsigned)h4.y << 16) | (unsigned)t4.y;
            if (a2) g_list[off++] = (((unsigned long long)r4v.z) << 32) | ((unsigned)tl4.z << 16) | (unsigned)h4.z;
            if (b2) g_list[off++] = (((unsigned long long)(r4v.z + RRR)) << 32) | ((unsigned)h4.z << 16) | (unsigned)t4.z;
            if (a3) g_list[off++] = (((unsigned long long)r4v.w) << 32) | ((unsigned)tl4.w << 16) | (unsigned)h4.w;
            if (b3) g_list[off++] = (((unsigned long long)(r4v.w + RRR)) << 32) | ((unsigned)h4.w << 16) | (unsigned)t4.w;
        }
    }
}

// ---------------- propagate over packed list + accumulate sums ----------------
__global__ void prop_kernel(int t) {
    __shared__ float sm[8][32];
    int lane = threadIdx.x & 31;
    int warp = (blockIdx.x * blockDim.x + threadIdx.x) >> 5;
    int nw = (gridDim.x * blockDim.x) >> 5;
    const float* wt = &g_w[t * NRELC * K32];
    int cnt = g_cnt[0];
    float sacc = 0.0f;

    for (int j0 = warp * 6; j0 < cnt; j0 += nw * 6) {
        int n = min(6, cnt - j0);
        unsigned long long e[6];
        #pragma unroll
        for (int u = 0; u < 6; u++) if (u < n) e[u] = g_list[j0 + u];
        float xv[6], wv[6];
        #pragma unroll
        for (int u = 0; u < 6; u++) if (u < n) {
            int src = (int)(e[u] & 0xFFFFu);
            int rel = (int)(e[u] >> 32);
            xv[u] = g_x[src * K32 + lane];
            wv[u] = wt[rel * K32 + lane];
        }
        #pragma unroll
        for (int u = 0; u < 6; u++) if (u < n) {
            int dst = (int)((e[u] >> 16) & 0xFFFFu);
            float mm = xv[u] * wv[u];
            sacc += mm;
            if (mm != 0.0f) atomicAdd(&g_s[dst * K32 + lane], mm);
        }
    }
    sm[threadIdx.x >> 5][lane] = sacc;
    __syncthreads();
    if (threadIdx.x < 32) {
        float s = 0.0f;
        #pragma unroll
        for (int w = 0; w < 8; w++) s += sm[w][threadIdx.x];
        if (s != 0.0f) atomicAdd(&g_sums[t][threadIdx.x], s);
    }
}

// ---------------- select_build: block-aggregated nzc + sel + buildx (512 blocks) ----------------
__global__ __launch_bounds__(256, 4) void select_build_kernel(int t) {
    const int blk = blockIdx.x, tid = threadIdx.x;
    const int lane = tid & 31, warp = tid >> 5;
    const int gtid = blk * 256 + tid;
    __shared__ unsigned s_h[256], s_scan[256];
    __shared__ unsigned s_pref, s_need;
    __shared__ float sm[8][32];
    __shared__ int s_cnt[24], s_base[24], s_idx[24];

    // ---- phase 1: nzc with block-aggregated counter reservation ----
    // Each block owns a contiguous slab of rows; two passes over the (L1-hot) slab:
    // count nonzeros per channel, reserve one global chunk per channel, scatter.
    {
        const int SLAB = (EE + NBSB - 1) / NBSB;   // 98
        int beg = blk * SLAB, end = min(beg + SLAB, EE);
        if (tid < 24) s_cnt[tid] = 0;
        __syncthreads();
        for (int i = beg * K32 + tid; i < end * K32; i += 256) {
            int k = i & 31;      // constant per thread (stride 256)
            if (k < 24 && g_s[i] != 0.0f) atomicAdd(&s_cnt[k], 1);
        }
        __syncthreads();
        if (tid < 24) { s_base[tid] = atomicAdd(&g_ccnt[tid], s_cnt[tid]); s_idx[tid] = 0; }
        __syncthreads();
        for (int i = beg * K32 + tid; i < end * K32; i += 256) {
            int k = i & 31;
            if (k < 24) {
                float v = g_s[i];
                if (v != 0.0f) {
                    int o = atomicAdd(&s_idx[k], 1);
                    g_cand[k * EE + s_base[k] + o] = __float_as_uint(v);
                }
            }
        }
    }
    gbarSB();

    // ---- phase 2: exact top-k threshold (blocks 0..23) ----
    if (blk < 24) {
        int k = blk;
        int cnt = g_ccnt[k];
        if (cnt < TOPKC) {
            if (tid == 0) g_th[k] = 0.0f;
        } else {
            unsigned pref = 0, need = TOPKC;
            const unsigned* cand = &g_cand[k * EE];
            for (int p = 3; p >= 0; p--) {
                s_h[tid] = 0u;
                __syncthreads();
                for (int i = tid; i < cnt; i += 256) {
                    unsigned u = cand[i];
                    bool ok = (p == 3) || ((u >> (8 * p + 8)) == pref);
                    if (ok) atomicAdd(&s_h[(u >> (8 * p)) & 255u], 1u);
                }
                __syncthreads();
                s_scan[tid] = s_h[tid];
                __syncthreads();
                for (int o = 1; o < 256; o <<= 1) {
                    unsigned add = (tid + o < 256) ? s_scan[tid + o] : 0u;
                    __syncthreads();
                    s_scan[tid] += add;
                    __syncthreads();
                }
                unsigned cumIncl = s_scan[tid];
                unsigned cumAbove = cumIncl - s_h[tid];
                if (cumIncl >= need && cumAbove < need) {
                    s_pref = (pref << 8) | (unsigned)tid;
                    s_need = need - cumAbove;
                }
                __syncthreads();
                pref = s_pref; need = s_need;
                __syncthreads();
            }
            if (tid == 0) g_th[k] = __uint_as_float(pref);
        }
    }
    gbarSB();

    // ---- phase 3: buildx for hop t ----
    {
        if (gtid == 0) g_cnt[0] = 0;
        const int NWRP = NBSB * 8;
        int gwarp = blk * 8 + warp;
        float wid = g_w[(t * NRELC + (NRELC - 1)) * K32 + lane];
        float th = g_th[lane];
        float den = fmaxf(g_sums[t - 1][lane], 1e-7f);
        float sacc = 0.0f;
        for (int e = gwarp; e < EE; e += NWRP) {
            float v = g_s[e * K32 + lane];
            float x = (v >= th) ? (v / den) : 0.0f;
            unsigned nz = __ballot_sync(0xFFFFFFFFu, x != 0.0f);
            if (nz) g_x[e * K32 + lane] = x;
            float s = wid * x;
            g_s[e * K32 + lane] = s;
            sacc += s;
            if (lane == 0) g_actb[e] = nz ? 1 : 0;
        }
        __syncthreads();
        sm[warp][lane] = sacc;
        __syncthreads();
        if (tid < 32) {
            float s = 0.0f;
            #pragma unroll
            for (int w = 0; w < 8; w++) s += sm[w][tid];
            if (s != 0.0f) atomicAdd(&g_sums[t][tid], s);
        }
    }
}

// ---------------- final output: transposed coalesced writes ----------------
__global__ void out_kernel(float* __restrict__ out) {
    __shared__ float s_tile[8][32][33];
    __shared__ float s_den[24];
    int tid = threadIdx.x, lane = tid & 31, warp = tid >> 5;
    if (tid < 24) s_den[tid] = 1.0f / fmaxf(g_sums[TT - 1][tid], 1e-7f);
    __syncthreads();
    int gwarp = blockIdx.x * 8 + warp;
    int nw = gridDim.x * 8;
    for (int e0 = gwarp * 32; e0 < EE; e0 += nw * 32) {
        #pragma unroll 4
        for (int j = 0; j < 32; j++) {
            int e = e0 + j;
            s_tile[warp][j][lane] = (e < EE) ? g_s[e * K32 + lane] : 0.0f;
        }
        __syncwarp();
        int e = e0 + lane;
        if (e < EE) {
            #pragma unroll
            for (int b = 0; b < 8; b++) {
                float a = 0.0f;
                #pragma unroll
                for (int l = 0; l < 3; l++)
                    a += s_tile[warp][lane][b * 3 + l] * s_den[b * 3 + l];
                out[b * EE + e] = a;
            }
        }
        __syncwarp();
    }
}

// ---------------- launch ----------------
extern "C" void kernel_launch(void* const* d_in, const int* in_sizes, int n_in,
                              void* d_out, int out_size) {
    const int*   input_x  = (const int*)d_in[0];
    const int*   input_r  = (const int*)d_in[1];
    const int*   e2triple = (const int*)d_in[2];
    const int*   triple2e = (const int*)d_in[3];
    const int*   r2triple = (const int*)d_in[4];
    const float* emb      = (const float*)d_in[5];
    const float* Wih_f    = (const float*)d_in[6];
    const float* Whh_f    = (const float*)d_in[7];
    const float* bih_f    = (const float*)d_in[8];
    const float* bhh_f    = (const float*)d_in[9];
    const float* Wih_b    = (const float*)d_in[10];
    const float* Whh_b    = (const float*)d_in[11];
    const float* bih_b    = (const float*)d_in[12];
    const float* bhh_b    = (const float*)d_in[13];
    const float* linW     = (const float*)d_in[14];
    const float* linb     = (const float*)d_in[15];

    const int* heads  = e2triple;
    const int* tails2 = e2triple + 2 * NN;
    const int* tails  = triple2e + NN;
    const int* rels   = r2triple;

    pre_kernel<<<dim3(128, 6), 256>>>(input_r, emb, Wih_f, bih_f, bhh_f,
                                      Wih_b, bih_b, bhh_b);
    lstm_rec_kernel<<<NB_LSTM, 256>>>(Whh_f, Whh_b, linW, linb);

    for (int t = 0; t < TT; t++) {
        if (t == 0) buildx0_kernel<<<512, 256>>>(input_x);
        else        select_build_kernel<<<NBSB, 256>>>(t);
        compact_kernel<<<1024, 256>>>(heads, tails, tails2, rels);
        prop_kernel<<<1024, 256>>>(t);
    }

    out_kernel<<<256, 256>>>((float*)d_out);
}